// round 17
// baseline (speedup 1.0000x reference)
#include <cuda_runtime.h>
#include <cuda_fp16.h>
#include <cstring>

// CombinedPriorityLoss, single fused kernel:
//   Phase A: 64 chunk-blocks -> per-chunk bin histogram (65 bins) + moments
//   grid barrier
//   Phase B: 64 chunk-blocks -> deterministic stable bin-sort scatter
//   grid barrier
//   Phase C: 1056 triangle tiles over sorted array; corner-bin classification
//            (pure-relu / pure-mid 3-op fp16x2 loops, ~4% general PAIR2)
//   ticket finalize (deterministic), resets barrier/ticket for graph replay.
// Grid is single-wave resident (1056 blocks x 128thr) -> spin barrier safe.

#define MARGIN 0.2f

constexpr int NBIN = 65;
constexpr int MAXN = 8192;
constexpr int MAXCH = MAXN / 128;     // 64
constexpr int MAXPB = 2080;

__device__ float g_ps[MAXN];
__device__ float g_ts[MAXN];
__device__ __align__(16) __half g_ph[MAXN];   // fp16(-0.1*p), bin-sorted
__device__ __align__(16) __half g_th[MAXN];   // fp16(-t), bin-sorted
__device__ int    g_h[MAXCH][NBIN];
__device__ float  g_mom[MAXCH][5];
__device__ float  g_part[MAXPB];
__device__ unsigned g_ticket = 0;
__device__ unsigned g_bar_count = 0;
__device__ volatile unsigned g_bar_gen = 0;

__device__ __forceinline__ int bin_of(float t) {
    return min(NBIN - 1, max(0, (int)(t * 65.0f)));
}
__device__ __forceinline__ __half2 uh(unsigned u) {
    __half2 h; memcpy(&h, &u, 4); return h;
}
__device__ __forceinline__ unsigned hu(__half2 h) {
    unsigned u; memcpy(&u, &h, 4); return u;
}

__device__ __forceinline__ void grid_barrier(int nblocks, unsigned phase) {
    __syncthreads();
    if (threadIdx.x == 0) {
        __threadfence();
        unsigned t = atomicAdd(&g_bar_count, 1u);
        if (t == (unsigned)nblocks - 1u) {
            g_bar_count = 0;
            __threadfence();
            g_bar_gen = phase;
        } else {
            while (g_bar_gen < phase) { }
            __threadfence();
        }
    }
    __syncthreads();
}

__global__ __launch_bounds__(128)
void fused(const float* __restrict__ pred, const float* __restrict__ tgt,
           int N, int nC, float* __restrict__ out) {
    const int bid = blockIdx.x, nblocks = gridDim.x;
    const int tid = threadIdx.x, lane = tid & 31, wid = tid >> 5;
    const int nchunks = nC;   // chunks of 128

    __shared__ int wcnt[4][NBIN];
    __shared__ int stot[NBIN], sstart[NBIN];
    __shared__ float red[4][5];
    __shared__ int s_last;

    // ================= Phase A: per-chunk histogram + moments ==============
    if (bid < nchunks) {
        for (int k = tid; k < 4 * NBIN; k += 128) ((int*)wcnt)[k] = 0;
        __syncthreads();
        int i = bid * 128 + tid;
        bool valid = (i < N);
        float p = 0.f, t = 0.f;
        int b = NBIN;   // sentinel
        if (valid) { p = pred[i]; t = tgt[i]; b = bin_of(t); }
        unsigned mk = __match_any_sync(0xffffffffu, b);
        if (valid && (mk & (0u - mk)) == (1u << lane))
            wcnt[wid][b] = __popc(mk);
        // moments
        float d = p - t;
        float m[5] = { d * d, p, p * p, t, t * t };
        #pragma unroll
        for (int k = 0; k < 5; k++) {
            float v = m[k];
            #pragma unroll
            for (int o = 16; o; o >>= 1) v += __shfl_down_sync(0xffffffffu, v, o);
            if (lane == 0) red[wid][k] = v;
        }
        __syncthreads();
        if (tid < NBIN)
            g_h[bid][tid] = wcnt[0][tid] + wcnt[1][tid] + wcnt[2][tid] + wcnt[3][tid];
        if (tid == 0) {
            #pragma unroll
            for (int k = 0; k < 5; k++)
                g_mom[bid][k] = red[0][k] + red[1][k] + red[2][k] + red[3][k];
        }
    }
    grid_barrier(nblocks, 1);

    // ================= Phase B: stable bin-sort scatter ====================
    if (bid < nchunks) {
        for (int k = tid; k < 4 * NBIN; k += 128) ((int*)wcnt)[k] = 0;
        __syncthreads();
        int i = bid * 128 + tid;
        bool valid = (i < N);
        float p = 0.f, t = 0.f;
        int b = NBIN;
        if (valid) { p = pred[i]; t = tgt[i]; b = bin_of(t); }
        unsigned mk = __match_any_sync(0xffffffffu, b);
        int lrank = __popc(mk & ((1u << lane) - 1u));
        if (valid && (mk & (0u - mk)) == (1u << lane))
            wcnt[wid][b] = __popc(mk);
        // bin totals across chunks
        if (tid < NBIN) {
            int s = 0;
            for (int c = 0; c < nchunks; c++) s += g_h[c][tid];
            stot[tid] = s;
        }
        __syncthreads();
        if (tid == 0) {
            int s = 0;
            for (int bb = 0; bb < NBIN; bb++) { sstart[bb] = s; s += stot[bb]; }
        }
        __syncthreads();
        if (valid) {
            int base = sstart[b];
            for (int c = 0; c < bid; c++) base += g_h[c][b];
            int r = lrank;
            #pragma unroll
            for (int w = 0; w < 4; w++) if (w < wid) r += wcnt[w][b];
            int pos = base + r;
            g_ps[pos] = p;
            g_ts[pos] = t;
            g_ph[pos] = __float2half_rn(-0.1f * p);
            g_th[pos] = __float2half_rn(-t);
        }
    }
    grid_barrier(nblocks, 2);

    // ================= Phase C: classified triangle tiles ==================
    float accC = 0.f;
    {
        // decode (TI, tj): cum(TI) = TI*(nC+1-TI), tj in [2TI, nC)
        int TI = 0;
        while ((TI + 1) * (nC - TI) <= bid) TI++;
        const int tj = 2 * TI + (bid - TI * (nC + 1 - TI));
        const int dd = tj - 2 * TI;
        const float w0 = (dd == 0) ? 0.5f : 1.f;
        const float w1 = (dd == 0) ? 0.f : ((dd == 1) ? 0.5f : 1.f);

        __shared__ __align__(16) __half sPh[128];
        __shared__ __align__(16) __half sTh[128];

        const int cl = tj * 128;
        const bool colpad = (cl + 127 >= N);
        {
            int j = cl + tid;
            sPh[tid] = (j < N) ? g_ph[j] : __float2half_rn(-3000.f);
            sTh[tid] = (j < N) ? g_th[j] : __float2half_rn(-30000.f);
        }
        __syncthreads();

        const __half2 Z2 = __float2half2_rn(0.f);
        const __half2 M2 = __float2half2_rn(MARGIN);
        const __half2 TEN2 = __float2half2_rn(10.f);
        const uint4* cp4 = (const uint4*)sPh;
        const uint4* ct4 = (const uint4*)sTh;

        const int bC = bin_of(g_ts[min(cl, N - 1)]);
        const int bD = bin_of(g_ts[min(cl + 127, N - 1)]);

        #pragma unroll
        for (int r = 0; r < 2; r++) {
            const float wr = r ? w1 : w0;
            if (wr == 0.f) continue;
            const int rbase = TI * 256 + r * 128;
            const int i = rbase + tid;
            const int bA = bin_of(g_ts[min(rbase, N - 1)]);
            const int bB = bin_of(g_ts[min(rbase + 127, N - 1)]);
            int flavor = 2;
            if (!colpad) {
                if (bC - bB >= 14)      flavor = 0;   // pure relu
                else if (bD - bA <= 12) flavor = 1;   // pure mid
            }
            const bool rowreal = (i < N);
            const float pi = rowreal ? g_ps[i] : 30000.f;
            const float ti = rowreal ? g_ts[i] : 30000.f;

            if (flavor == 0) {
                __half2 a2 = __float2half2_rn(0.02f + 0.1f * pi);
                __half2 c0 = Z2, c1 = Z2, c2 = Z2, c3 = Z2;
                #pragma unroll 4
                for (int k = 0; k < 16; k++) {
                    uint4 v = cp4[k];
                    c0 = __hadd2(c0, __hmax2(__hadd2(a2, uh(v.x)), Z2));
                    c1 = __hadd2(c1, __hmax2(__hadd2(a2, uh(v.y)), Z2));
                    c2 = __hadd2(c2, __hmax2(__hadd2(a2, uh(v.z)), Z2));
                    c3 = __hadd2(c3, __hmax2(__hadd2(a2, uh(v.w)), Z2));
                }
                __half2 cs = __hadd2(__hadd2(c0, c1), __hadd2(c2, c3));
                if (rowreal)
                    accC += wr * 10.f * (__low2float(cs) + __high2float(cs));
            } else if (flavor == 1) {
                __half2 p2 = __float2half2_rn(0.1f * pi);
                __half2 c0 = Z2, c1 = Z2, c2 = Z2, c3 = Z2;
                #pragma unroll 4
                for (int k = 0; k < 16; k++) {
                    uint4 v = cp4[k];
                    c0 = __hadd2(c0, __habs2(__hadd2(p2, uh(v.x))));
                    c1 = __hadd2(c1, __habs2(__hadd2(p2, uh(v.y))));
                    c2 = __hadd2(c2, __habs2(__hadd2(p2, uh(v.z))));
                    c3 = __hadd2(c3, __habs2(__hadd2(p2, uh(v.w))));
                }
                __half2 cs = __hadd2(__hadd2(c0, c1), __hadd2(c2, c3));
                if (rowreal)
                    accC += wr * (__low2float(cs) + __high2float(cs));
            } else {
                const unsigned pi2 = hu(__float2half2_rn(0.1f * pi));
                const unsigned ti2 = hu(__float2half2_rn(ti));
                __half2 a0 = Z2, a1 = Z2, aq = Z2, a3 = Z2;
                #define PAIR2(vpu, vtu, acc) {                                \
                    unsigned dpu = hu(__hadd2(uh(pi2), uh(vpu)));             \
                    unsigned dtu = hu(__hadd2(uh(ti2), uh(vtu)));             \
                    unsigned qxu = dpu ^ 0x80008000u ^ (dtu & 0x80008000u);   \
                    __half2 r2 = __hmax2(__hfma2(uh(qxu), TEN2, M2), Z2);     \
                    unsigned mm = __hgt2_mask(uh(dtu & 0x7FFF7FFFu), M2);     \
                    unsigned vs = (hu(r2) & mm) | ((dpu & 0x7FFF7FFFu) & ~mm);\
                    acc = __hadd2(acc, uh(vs)); }
                #pragma unroll 4
                for (int k = 0; k < 16; k++) {
                    uint4 vp = cp4[k];
                    uint4 vt = ct4[k];
                    PAIR2(vp.x, vt.x, a0);
                    PAIR2(vp.y, vt.y, a1);
                    PAIR2(vp.z, vt.z, aq);
                    PAIR2(vp.w, vt.w, a3);
                }
                #undef PAIR2
                __half2 cs = __hadd2(__hadd2(a0, a1), __hadd2(aq, a3));
                accC += wr * (__low2float(cs) + __high2float(cs));
            }
        }
    }

    // block reduction
    #pragma unroll
    for (int o = 16; o; o >>= 1)
        accC += __shfl_down_sync(0xffffffffu, accC, o);
    if (lane == 0) red[wid][0] = accC;
    __syncthreads();
    if (tid == 0)
        g_part[bid] = red[0][0] + red[1][0] + red[2][0] + red[3][0];

    // ---- deterministic last-block finalize ----
    __threadfence();
    if (tid == 0) {
        unsigned t = atomicAdd(&g_ticket, 1u);
        s_last = (t == (unsigned)(nblocks - 1));
    }
    __syncthreads();
    if (!s_last) return;

    double rA = 0.0;
    for (int k = tid; k < nblocks; k += 128) rA += (double)g_part[k];
    __shared__ double dred[4];
    #pragma unroll
    for (int o = 16; o; o >>= 1) rA += __shfl_down_sync(0xffffffffu, rA, o);
    if (lane == 0) dred[wid] = rA;
    __syncthreads();
    if (tid == 0) {
        double A = dred[0] + dred[1] + dred[2] + dred[3];
        double mom[5] = {0, 0, 0, 0, 0};
        for (int c = 0; c < nchunks; c++)
            for (int k = 0; k < 5; k++) mom[k] += (double)g_mom[c][k];
        double n = (double)N;
        double mse = mom[0] / n;
        double pred_var = (mom[2] - mom[1] * mom[1] / n) / (n - 1.0);
        double tgt_var  = (mom[4] - mom[3] * mom[3] / n) / (n - 1.0);
        double div = tgt_var - pred_var;
        if (div < 0.0) div = 0.0;
        long long pc = (long long)N * (N - 1) / 2;
        if (pc < 1) pc = 1;
        double rank = A / (double)pc;
        out[0] = (float)(0.1 * mse + 0.9 * rank + 0.1 * div);
        g_ticket = 0;
        g_bar_gen = 0;   // reset barrier generation for next graph replay
    }
}

extern "C" void kernel_launch(void* const* d_in, const int* in_sizes, int n_in,
                              void* d_out, int out_size) {
    const float* pred = (const float*)d_in[0];
    const float* tgt  = (const float*)d_in[1];
    float* out = (float*)d_out;
    int N = in_sizes[0];
    int nC = (N + 127) / 128;
    int nR = (nC + 1) / 2;
    int nblocks = nR * (nC + 1 - nR);   // 1056 @ N=8192 (>= nC always)
    fused<<<nblocks, 128>>>(pred, tgt, N, nC, out);
}